// round 14
// baseline (speedup 1.0000x reference)
#include <cuda_runtime.h>
#include <cuda_fp16.h>
#include <cstdint>

#define Nn   5000
#define Bb   16
#define MP   5120          // padded node dim, 40*128 = 32*160
#define NK   80            // MP/64 k-chunks

// ---------------- scratch (device globals, zero-initialized at load) ----------------
__device__ __half g_Eh[(size_t)MP * 64];
__device__ __half g_El[(size_t)MP * 64];
__device__ float g_rowmax[MP];
__device__ float g_rsp[2][MP];
__device__ __half g_Ph[(size_t)MP * MP];
__device__ __half g_xT_h[(size_t)512 * MP];
__device__ __half g_y1T_h[(size_t)512 * MP];
__device__ float g_y1[(size_t)Nn * 512];
__device__ float g_y2[(size_t)Nn * 512];
__device__ __half g_WT[(size_t)3584 * 64];
__device__ __half g_W16[(size_t)MP * 3584];
__device__ float g_xwagg[Nn * Bb * 16];

// ---------------- base-ISA tensor helpers ----------------
__device__ __forceinline__ void cpa16(uint32_t s, const void* g) {
    asm volatile("cp.async.cg.shared.global [%0], [%1], 16;" :: "r"(s), "l"(g) : "memory");
}
__device__ __forceinline__ void ldsm4(uint32_t* r, uint32_t a) {
    asm volatile("ldmatrix.sync.aligned.m8n8.x4.shared.b16 {%0,%1,%2,%3}, [%4];"
                 : "=r"(r[0]), "=r"(r[1]), "=r"(r[2]), "=r"(r[3]) : "r"(a));
}
__device__ __forceinline__ void ldsm2(uint32_t* r, uint32_t a) {
    asm volatile("ldmatrix.sync.aligned.m8n8.x2.shared.b16 {%0,%1}, [%2];"
                 : "=r"(r[0]), "=r"(r[1]) : "r"(a));
}
__device__ __forceinline__ void mma_h(float* d, const uint32_t* a, const uint32_t* b) {
    asm volatile("mma.sync.aligned.m16n8k16.row.col.f32.f16.f16.f32 "
                 "{%0,%1,%2,%3}, {%4,%5,%6,%7}, {%8,%9}, {%0,%1,%2,%3};"
                 : "+f"(d[0]), "+f"(d[1]), "+f"(d[2]), "+f"(d[3])
                 : "r"(a[0]), "r"(a[1]), "r"(a[2]), "r"(a[3]), "r"(b[0]), "r"(b[1]));
}
__device__ __forceinline__ uint32_t pack2h(float a, float b) {
    __half2 h = __halves2half2(__float2half_rn(a), __float2half_rn(b));
    return *(uint32_t*)&h;
}
__device__ __forceinline__ uint32_t smem_u32(const void* p) {
    uint32_t r;
    asm("{ .reg .u64 t; cvta.to.shared.u64 t, %1; cvt.u32.u64 %0, t; }" : "=r"(r) : "l"(p));
    return r;
}

// ---------------- prep ----------------
__global__ void prep_kernel(const float* __restrict__ x, const float* __restrict__ emb,
                            const float* __restrict__ wp, const float* __restrict__ wwin) {
    __shared__ float t[64][65];
    if (blockIdx.x < 632) {
        int mt = blockIdx.x % 79, jt = blockIdx.x / 79;
        int m0 = mt * 64, j0 = jt * 64;
        #pragma unroll
        for (int q = 0; q < 16; q++) {
            int f = threadIdx.x + 256 * q;
            int mr = f >> 6, jj = f & 63;
            int m = m0 + mr, j = j0 + jj;
            float v = (m < Nn) ? x[(((size_t)(j >> 5)) * Nn + m) * 32 + (j & 31)] : 0.0f;
            t[jj][mr] = v;
        }
        __syncthreads();
        #pragma unroll
        for (int q = 0; q < 16; q++) {
            int f = threadIdx.x + 256 * q;
            int jj = f >> 6, mr = f & 63;
            int m = m0 + mr;
            if (m < Nn)
                g_xT_h[(size_t)(j0 + jj) * MP + m] = __float2half_rn(t[jj][mr]);
        }
    } else if (blockIdx.x < 652) {
        int gid = (blockIdx.x - 632) * 256 + threadIdx.x;
        for (int i = gid; i < Nn * 64; i += 20 * 256) {
            float v = emb[i];
            __half h = __float2half_rn(v);
            g_Eh[i] = h;
            g_El[i] = __float2half_rn(v - __half2float(h));
        }
    } else {
        int j = (blockIdx.x - 652) * 256 + threadIdx.x;
        #pragma unroll 8
        for (int d = 0; d < 64; d++) {
            float v = (j < 3072) ? wp[(size_t)d * 3072 + j]
                                 : wwin[(size_t)d * 512 + (j - 3072)];
            g_WT[(size_t)j * 64 + d] = __float2half_rn(v);
        }
    }
}

// ---------------- rowmax ----------------
__global__ void __launch_bounds__(256) rowmax_tc() {
    __shared__ __align__(16) char sm[33280];
    uint32_t raw = smem_u32(sm);
    uint32_t SAH = raw, SBH = raw + 16384;
    unsigned* smax = (unsigned*)(sm + 32768);
    int tid = threadIdx.x, lane = tid & 31, wid = tid >> 5;
    int wm = wid >> 2, wn = wid & 3;
    int m0 = blockIdx.y * 128, nb = blockIdx.x * 2560;

    #pragma unroll
    for (int q = 0; q < 4; q++) {
        int u = tid + 256 * q;
        int row = u >> 3, c16 = u & 7;
        uint4 v = *(const uint4*)(g_Eh + (size_t)(m0 + row) * 64 + c16 * 8);
        *(uint4*)(sm + (row * 128 + ((c16 ^ (row & 7)) * 16))) = v;
    }
    if (tid < 128) smax[tid] = 0u;
    __syncthreads();

    int hb = lane >> 4, bbit = (lane >> 3) & 1;
    uint32_t a_off[4], a7[4], b_off[4], b7[4];
    #pragma unroll
    for (int mf = 0; mf < 4; mf++) {
        int ar = wm * 64 + mf * 16 + (lane & 15);
        a_off[mf] = (uint32_t)(ar * 128); a7[mf] = (uint32_t)(ar & 7);
    }
    #pragma unroll
    for (int nf = 0; nf < 4; nf++) {
        int br = wn * 32 + nf * 8 + (lane & 7);
        b_off[nf] = (uint32_t)(br * 128); b7[nf] = (uint32_t)(br & 7);
    }

    float rmx[4][2];
    #pragma unroll
    for (int mf = 0; mf < 4; mf++) { rmx[mf][0] = 0.0f; rmx[mf][1] = 0.0f; }

    for (int sub = 0; sub < 20; sub++) {
        int n0 = nb + sub * 128;
        #pragma unroll
        for (int q = 0; q < 4; q++) {
            int u = tid + 256 * q;
            int row = u >> 3, c16 = u & 7;
            uint4 v = *(const uint4*)(g_Eh + (size_t)(n0 + row) * 64 + c16 * 8);
            *(uint4*)(sm + 16384 + (row * 128 + ((c16 ^ (row & 7)) * 16))) = v;
        }
        __syncthreads();
        float acc[4][4][4];
        #pragma unroll
        for (int mf = 0; mf < 4; mf++)
            #pragma unroll
            for (int nf = 0; nf < 4; nf++)
                #pragma unroll
                for (int e = 0; e < 4; e++) acc[mf][nf][e] = 0.0f;
        #pragma unroll
        for (int ks = 0; ks < 4; ks++) {
            uint32_t af[4][4], bfx[4][2];
            uint32_t ca = (uint32_t)(ks * 2 + hb), cb = (uint32_t)(ks * 2 + bbit);
            #pragma unroll
            for (int mf = 0; mf < 4; mf++) ldsm4(af[mf], SAH + a_off[mf] + ((ca ^ a7[mf]) << 4));
            #pragma unroll
            for (int nf = 0; nf < 4; nf++) ldsm2(bfx[nf], SBH + b_off[nf] + ((cb ^ b7[nf]) << 4));
            #pragma unroll
            for (int mf = 0; mf < 4; mf++)
                #pragma unroll
                for (int nf = 0; nf < 4; nf++) mma_h(acc[mf][nf], af[mf], bfx[nf]);
        }
        #pragma unroll
        for (int mf = 0; mf < 4; mf++)
            #pragma unroll
            for (int nf = 0; nf < 4; nf++) {
                rmx[mf][0] = fmaxf(rmx[mf][0], fmaxf(acc[mf][nf][0], acc[mf][nf][1]));
                rmx[mf][1] = fmaxf(rmx[mf][1], fmaxf(acc[mf][nf][2], acc[mf][nf][3]));
            }
        __syncthreads();
    }
    int g = lane >> 2;
    #pragma unroll
    for (int mf = 0; mf < 4; mf++) {
        int r1 = wm * 64 + mf * 16 + g;
        atomicMax(&smax[r1], __float_as_uint(rmx[mf][0]));
        atomicMax(&smax[r1 + 8], __float_as_uint(rmx[mf][1]));
    }
    __syncthreads();
    if (tid < 128) atomicMax((unsigned*)&g_rowmax[m0 + tid], smax[tid]);
}

// ---------------- pexp: 80 CTAs (one wave), 20 subs each ----------------
#define PE_SMEM 101376
__global__ void __launch_bounds__(256) pexp_tc() {
    extern __shared__ char sm[];
    uint32_t raw = smem_u32(sm);
    uint32_t SAH = raw, SAL = raw + 16384, SBH = raw + 32768, SBL = raw + 49152;
    float* stg   = (float*)(sm + 32768);
    float* rsum  = (float*)(sm + 100352);
    float* rmaxS = (float*)(sm + 100864);

    int tid = threadIdx.x, lane = tid & 31, wid = tid >> 5;
    int wm = wid >> 2, wn = wid & 3;
    int m0 = blockIdx.y * 128, nc0 = blockIdx.x * 2560;

    #pragma unroll
    for (int q = 0; q < 8; q++) {
        int id = tid + 256 * q;
        int hf = id >> 10, u = id & 1023;
        int row = u >> 3, c16 = u & 7;
        const __half* src = hf ? g_El : g_Eh;
        uint4 v = *(const uint4*)(src + (size_t)(m0 + row) * 64 + c16 * 8);
        *(uint4*)(sm + (hf ? 16384 : 0) + row * 128 + ((c16 ^ (row & 7)) * 16)) = v;
    }
    if (tid < 128) { rsum[tid] = 0.0f; rmaxS[tid] = g_rowmax[m0 + tid]; }
    __syncthreads();

    int hb = lane >> 4, bbit = (lane >> 3) & 1;
    uint32_t a_off[4], a7[4], b_off[4], b7[4];
    #pragma unroll
    for (int mf = 0; mf < 4; mf++) {
        int ar = wm * 64 + mf * 16 + (lane & 15);
        a_off[mf] = (uint32_t)(ar * 128); a7[mf] = (uint32_t)(ar & 7);
    }
    #pragma unroll
    for (int nf = 0; nf < 4; nf++) {
        int br = wn * 32 + nf * 8 + (lane & 7);
        b_off[nf] = (uint32_t)(br * 128); b7[nf] = (uint32_t)(br & 7);
    }

    for (int sub = 0; sub < 20; sub++) {
        int n0 = nc0 + sub * 128;
        #pragma unroll
        for (int q = 0; q < 8; q++) {
            int id = tid + 256 * q;
            int hf = id >> 10, u = id & 1023;
            int row = u >> 3, c16 = u & 7;
            const __half* src = hf ? g_El : g_Eh;
            uint4 v = *(const uint4*)(src + (size_t)(n0 + row) * 64 + c16 * 8);
            *(uint4*)(sm + (hf ? 49152 : 32768) + row * 128 + ((c16 ^ (row & 7)) * 16)) = v;
        }
        __syncthreads();

        float acc[4][4][4];
        #pragma unroll
        for (int mf = 0; mf < 4; mf++)
            #pragma unroll
            for (int nf = 0; nf < 4; nf++)
                #pragma unroll
                for (int e = 0; e < 4; e++) acc[mf][nf][e] = 0.0f;
        #pragma unroll
        for (int ks = 0; ks < 4; ks++) {
            uint32_t ah[4][4], al[4][4], bh[4][2], bl[4][2];
            uint32_t ca = (uint32_t)(ks * 2 + hb), cb = (uint32_t)(ks * 2 + bbit);
            #pragma unroll
            for (int mf = 0; mf < 4; mf++) {
                uint32_t xo = a_off[mf] + ((ca ^ a7[mf]) << 4);
                ldsm4(ah[mf], SAH + xo);
                ldsm4(al[mf], SAL + xo);
            }
            #pragma unroll
            for (int nf = 0; nf < 4; nf++) {
                uint32_t xo = b_off[nf] + ((cb ^ b7[nf]) << 4);
                ldsm2(bh[nf], SBH + xo);
                ldsm2(bl[nf], SBL + xo);
            }
            #pragma unroll
            for (int mf = 0; mf < 4; mf++)
                #pragma unroll
                for (int nf = 0; nf < 4; nf++) {
                    mma_h(acc[mf][nf], ah[mf], bh[nf]);
                    mma_h(acc[mf][nf], ah[mf], bl[nf]);
                    mma_h(acc[mf][nf], al[mf], bh[nf]);
                }
        }
        __syncthreads();

        int g = lane >> 2, t4 = lane & 3;
        #pragma unroll
        for (int mf = 0; mf < 4; mf++) {
            int r1 = wm * 64 + mf * 16 + g, r2 = r1 + 8;
            float mx1 = rmaxS[r1], mx2 = rmaxS[r2];
            #pragma unroll
            for (int nf = 0; nf < 4; nf++) {
                int c = wn * 32 + nf * 8 + t4 * 2;
                stg[r1 * 132 + c]     = __expf(fmaxf(acc[mf][nf][0], 0.0f) - mx1);
                stg[r1 * 132 + c + 1] = __expf(fmaxf(acc[mf][nf][1], 0.0f) - mx1);
                stg[r2 * 132 + c]     = __expf(fmaxf(acc[mf][nf][2], 0.0f) - mx2);
                stg[r2 * 132 + c + 1] = __expf(fmaxf(acc[mf][nf][3], 0.0f) - mx2);
            }
        }
        __syncthreads();

        if (tid < 128) {
            float s = 0.0f;
            #pragma unroll 8
            for (int c = 0; c < 128; c++) s += stg[tid * 132 + c];
            rsum[tid] += s;
        }
        #pragma unroll
        for (int q = 0; q < 8; q++) {
            int id = tid + 256 * q;
            int row = id >> 4, cu = id & 15;
            uint32_t wh[4];
            #pragma unroll
            for (int p = 0; p < 4; p++)
                wh[p] = pack2h(stg[row * 132 + cu * 8 + 2 * p],
                               stg[row * 132 + cu * 8 + 2 * p + 1]);
            *(uint4*)(g_Ph + (size_t)(m0 + row) * MP + n0 + cu * 8) =
                make_uint4(wh[0], wh[1], wh[2], wh[3]);
        }
        __syncthreads();
    }
    if (tid < 128) g_rsp[blockIdx.x][m0 + tid] = rsum[tid];
}

// ---------------- HMMA GEMM: split-k dual groups, cross-iter fragment pipeline ----------------
#define MT 160
#define JT 128
#define ABYTES 20480
#define BBYTES 16384
#define GSTG   (ABYTES + BBYTES)          // 36864 per stage
#define SMEM_BYTES (1024 + 6 * GSTG)      // 222208
#define SST 132

__global__ void __launch_bounds__(512, 1) tc_gemm(int which) {
    extern __shared__ char dsm[];
    uint32_t raw = smem_u32(dsm);
    uint32_t sb = (raw + 1023u) & ~1023u;

    int tid = threadIdx.x, lane = tid & 31, wid = tid >> 5;
    int grp = wid >> 3;
    int wg  = wid & 7;
    int wm = wg >> 2, wn = wg & 3;
    int gtid = tid & 255;
    int m0 = blockIdx.y * MT, j0 = blockIdx.x * JT;

    const __half* __restrict__ BT = which ? g_y1T_h : g_xT_h;

    uint32_t sA[5], sB[4];
    size_t gA[5], gB[4];
    #pragma unroll
    for (int q = 0; q < 5; q++) {
        int u = gtid + 256 * q;
        int row = u >> 3, c16 = u & 7;
        sA[q] = (uint32_t)(row * 128 + ((c16 ^ (row & 7)) * 16));
        gA[q] = (size_t)(m0 + row) * MP + c16 * 8;
    }
    #pragma unroll
    for (int q = 0; q < 4; q++) {
        int u = gtid + 256 * q;
        int row = u >> 3, c16 = u & 7;
        sB[q] = (uint32_t)(row * 128 + ((c16 ^ (row & 7)) * 16));
        gB[q] = (size_t)(j0 + row) * MP + c16 * 8;
    }

    // group g handles chunks t = 2l+g, stage = grp*3 + l%3
    auto issueg = [&](int l) {
        uint32_t base = sb + (uint32_t)(grp * 3 + l % 3) * GSTG;
        size_t ko = (size_t)(2 * l + grp) * 64;
        #pragma unroll
        for (int q = 0; q < 5; q++) cpa16(base + sA[q], g_Ph + gA[q] + ko);
        #pragma unroll
        for (int q = 0; q < 4; q++) cpa16(base + ABYTES + sB[q], BT + gB[q] + ko);
        asm volatile("cp.async.commit_group;" ::: "memory");
    };

    uint32_t a_off[5], a7[5], b_off[4], b7[4];
    int hb = lane >> 4, bbit = (lane >> 3) & 1;
    #pragma unroll
    for (int mf = 0; mf < 5; mf++) {
        int ar = wm * 80 + mf * 16 + (lane & 15);
        a_off[mf] = (uint32_t)(ar * 128); a7[mf] = (uint32_t)(ar & 7);
    }
    #pragma unroll
    for (int nf = 0; nf < 4; nf++) {
        int br = wn * 32 + nf * 8 + (lane & 7);
        b_off[nf] = (uint32_t)(br * 128); b7[nf] = (uint32_t)(br & 7);
    }

    float acc[5][4][4];
    #pragma unroll
    for (int mf = 0; mf < 5; mf++)
        #pragma unroll
        for (int nf = 0; nf < 4; nf++)
            #pragma unroll
            for (int e = 0; e < 4; e++) acc[mf][nf][e] = 0.0f;

    uint32_t af[2][5][4], bfr[2][4][2];

    // prologue: fill 3 stages, wait for first two, group barrier, prime ks0
    issueg(0); issueg(1); issueg(2);
    asm volatile("cp.async.wait_group 1;" ::: "memory");
    asm volatile("bar.sync %0, %1;" :: "r"(grp + 1), "r"(256) : "memory");
    {
        uint32_t Abuf = sb + (uint32_t)(grp * 3) * GSTG;
        uint32_t Bbuf = Abuf + ABYTES;
        uint32_t ca = (uint32_t)hb, cb = (uint32_t)bbit;
        #pragma unroll
        for (int mf = 0; mf < 5; mf++) ldsm4(af[0][mf], Abuf + a_off[mf] + ((ca ^ a7[mf]) << 4));
        #pragma unroll
        for (int nf = 0; nf < 4; nf++) ldsm2(bfr[0][nf], Bbuf + b_off[nf] + ((cb ^ b7[nf]) << 4));
    }

    for (int l = 0; l < 40; l++) {
        uint32_t Abuf = sb + (uint32_t)(grp * 3 + l % 3) * GSTG;
        uint32_t Bbuf = Abuf + ABYTES;
        uint32_t AbufN = sb + (uint32_t)(grp * 3 + (l + 1) % 3) * GSTG;
        uint32_t BbufN = AbufN + ABYTES;

        #pragma unroll
        for (int ks = 0; ks < 4; ks++) {
            int cur = ks & 1, nxt = cur ^ 1;
            if (ks < 3) {
                uint32_t ca = (uint32_t)((ks + 1) * 2 + hb), cb = (uint32_t)((ks + 1) * 2 + bbit);
                #pragma unroll
                for (int mf = 0; mf < 5; mf++) ldsm4(af[nxt][mf], Abuf + a_off[mf] + ((ca ^ a7[mf]) << 4));
                #pragma unroll
                for (int nf = 0; nf < 4; nf++) ldsm2(bfr[nxt][nf], Bbuf + b_off[nf] + ((cb ^ b7[nf]) << 4));
            } else if (l + 1 < 40) {
                // cross-iteration prefetch: next chunk's ks=0 from its (already-complete) stage
                uint32_t ca = (uint32_t)hb, cb = (uint32_t)bbit;
                #pragma unroll
                for (int mf = 0; mf < 5; mf++) ldsm4(af[nxt][mf], AbufN + a_off[mf] + ((ca ^ a7[mf]) << 4));
                #pragma unroll
                for (int nf = 0; nf < 4; nf++) ldsm2(bfr[nxt][nf], BbufN + b_off[nf] + ((cb ^ b7[nf]) << 4));
            }
            #pragma unroll
            for (int mf = 0; mf < 5; mf++)
                #pragma unroll
                for (int nf = 0; nf < 4; nf++)
                    mma_h(acc[mf][nf], af[cur][mf], bfr[cur][nf]);
        }
        // tail: wait (own groups) -> barrier (visibility + overwrite safety) -> issue
        if (l + 1 < 40) {
            asm volatile("cp.async.wait_group 1;" ::: "memory");
            asm volatile("bar.sync %0, %1;" :: "r"(grp + 1), "r"(256) : "memory");
            if (l + 3 < 40) issueg(l + 3);
        }
    }
    asm volatile("cp.async.wait_group 0;" ::: "memory");
    __syncthreads();   // both groups done; all async drained before smem reuse

    // ---- cross-group reduction + scale + writeout ----
    float* st = (float*)(dsm + (sb - raw));
    int g = lane >> 2, t4 = lane & 3;

    if (grp == 1) {
        #pragma unroll
        for (int mf = 0; mf < 5; mf++) {
            int r0 = wm * 80 + mf * 16 + g;
            #pragma unroll
            for (int nf = 0; nf < 4; nf++) {
                int c0 = wn * 32 + nf * 8 + t4 * 2;
                st[r0 * SST + c0]           = acc[mf][nf][0];
                st[r0 * SST + c0 + 1]       = acc[mf][nf][1];
                st[(r0 + 8) * SST + c0]     = acc[mf][nf][2];
                st[(r0 + 8) * SST + c0 + 1] = acc[mf][nf][3];
            }
        }
    }
    __syncthreads();
    if (grp == 0) {
        #pragma unroll
        for (int mf = 0; mf < 5; mf++) {
            int r0 = wm * 80 + mf * 16 + g;
            int ma = m0 + r0, mb = ma + 8;
            float al0 = 0.0f, al1 = 0.0f;
            if (ma < Nn) al0 = 1.0f / (g_rsp[0][ma] + g_rsp[1][ma]);
            if (mb < Nn) al1 = 1.0f / (g_rsp[0][mb] + g_rsp[1][mb]);
            #pragma unroll
            for (int nf = 0; nf < 4; nf++) {
                int c0 = wn * 32 + nf * 8 + t4 * 2;
                st[r0 * SST + c0]           = (acc[mf][nf][0] + st[r0 * SST + c0]) * al0;
                st[r0 * SST + c0 + 1]       = (acc[mf][nf][1] + st[r0 * SST + c0 + 1]) * al0;
                st[(r0 + 8) * SST + c0]     = (acc[mf][nf][2] + st[(r0 + 8) * SST + c0]) * al1;
                st[(r0 + 8) * SST + c0 + 1] = (acc[mf][nf][3] + st[(r0 + 8) * SST + c0 + 1]) * al1;
            }
        }
    }
    __syncthreads();

    float* __restrict__ Y = which ? g_y2 : g_y1;
    for (int u = tid; u < MT * 32; u += 512) {
        int r = u >> 5, ch = u & 31;
        int m = m0 + r;
        if (m < Nn) {
            float4 v = {st[r * SST + ch * 4],     st[r * SST + ch * 4 + 1],
                        st[r * SST + ch * 4 + 2], st[r * SST + ch * 4 + 3]};
            *(float4*)&Y[(size_t)m * 512 + j0 + ch * 4] = v;
        }
    }
    if (which == 0) {
        for (int u = tid; u < JT * 20; u += 512) {
            int j = u / 20, mm = u % 20;
            uint32_t w[4];
            #pragma unroll
            for (int p = 0; p < 4; p++)
                w[p] = pack2h(st[(mm * 8 + 2 * p) * SST + j],
                              st[(mm * 8 + 2 * p + 1) * SST + j]);
            *(uint4*)&g_y1T_h[(size_t)(j0 + j) * MP + m0 + mm * 8] =
                make_uint4(w[0], w[1], w[2], w[3]);
        }
    }
}

// ---------------- pool_tc ----------------
__global__ void __launch_bounds__(256) pool_tc() {
    __shared__ __align__(16) char sm[49152];
    uint32_t raw = smem_u32(sm);
    uint32_t SAH = raw, SAL = raw + 16384, SBH = raw + 32768;
    int tid = threadIdx.x, lane = tid & 31, wid = tid >> 5;
    int wm = wid >> 2, wn = wid & 3;
    int m0 = blockIdx.y * 128, j0 = blockIdx.x * 128;

    #pragma unroll
    for (int q = 0; q < 4; q++) {
        int u = tid + 256 * q;
        int row = u >> 3, c16 = u & 7;
        uint32_t so = (uint32_t)(row * 128 + ((c16 ^ (row & 7)) * 16));
        *(uint4*)(sm + so)          = *(const uint4*)(g_Eh + (size_t)(m0 + row) * 64 + c16 * 8);
        *(uint4*)(sm + 16384 + so)  = *(const uint4*)(g_El + (size_t)(m0 + row) * 64 + c16 * 8);
        *(uint4*)(sm + 32768 + so)  = *(const uint4*)(g_WT + (size_t)(j0 + row) * 64 + c16 * 8);
    }
    __syncthreads();

    int hb = lane >> 4, bbit = (lane >> 3) & 1;
    uint32_t a_off[4], a7[4], b_off[4], b7[4];
    #pragma unroll
    for (int mf = 0; mf < 4; mf++) {
        int ar = wm * 64 + mf * 16 + (lane & 15);
        a_off[mf] = (uint32_t)(ar * 128); a7[mf] = (uint32_t)(ar & 7);
    }
    #pragma unroll
    for (int nf = 0; nf < 4; nf++) {
        int br = wn * 32 + nf * 8 + (lane & 7);
        b_off[nf] = (uint32_t)(br * 128); b7[nf] = (uint32_t)(br & 7);
    }

    float acc[4][4][4];
    #pragma unroll
    for (int mf = 0; mf < 4; mf++)
        #pragma unroll
        for (int nf = 0; nf < 4; nf++)
            #pragma unroll
            for (int e = 0; e < 4; e++) acc[mf][nf][e] = 0.0f;

    #pragma unroll
    for (int ks = 0; ks < 4; ks++) {
        uint32_t ah[4][4], al[4][4], bh[4][2];
        uint32_t ca = (uint32_t)(ks * 2 + hb), cb = (uint32_t)(ks * 2 + bbit);
        #pragma unroll
        for (int mf = 0; mf < 4; mf++) {
            uint32_t xo = a_off[mf] + ((ca ^ a7[mf]) << 4);
            ldsm4(ah[mf], SAH + xo);
            ldsm4(al[mf], SAL + xo);
        }
        #pragma unroll
        for (int nf = 0; nf < 4; nf++) ldsm2(bh[nf], SBH + b_off[nf] + ((cb ^ b7[nf]) << 4));
        #pragma unroll
        for (int mf = 0; mf < 4; mf++)
            #pragma unroll
            for (int nf = 0; nf < 4; nf++) {
                mma_h(acc[mf][nf], ah[mf], bh[nf]);
                mma_h(acc[mf][nf], al[mf], bh[nf]);
            }
    }

    int g = lane >> 2, t4 = lane & 3;
    #pragma unroll
    for (int mf = 0; mf < 4; mf++) {
        int r1 = m0 + wm * 64 + mf * 16 + g;
        #pragma unroll
        for (int nf = 0; nf < 4; nf++) {
            int c = j0 + wn * 32 + nf * 8 + t4 * 2;
            *(uint32_t*)&g_W16[(size_t)r1 * 3584 + c] = pack2h(acc[mf][nf][0], acc[mf][nf][1]);
            *(uint32_t*)&g_W16[(size_t)(r1 + 8) * 3584 + c] = pack2h(acc[mf][nf][2], acc[mf][nf][3]);
        }
    }
}

// ---------------- xwagg ----------------
__global__ void xwagg_kernel(const float* __restrict__ xw, const float* __restrict__ T) {
    int idx = blockIdx.x * 256 + threadIdx.x;
    if (idx >= Nn * Bb * 16) return;
    int n = idx >> 8, r = idx & 255, b = r >> 4, i = r & 15;
    float s = 0.0f;
    #pragma unroll
    for (int t = 0; t < 12; t++)
        s = fmaf(__ldg(&T[t]), xw[(((size_t)b * 12 + t) * Nn + n) * 16 + i], s);
    g_xwagg[idx] = s;
}

// ---------------- fused epilogue ----------------
__global__ void __launch_bounds__(128) final_kernel(const float* __restrict__ x,
                                                    const float* __restrict__ emb,
                                                    const float* __restrict__ bpool,
                                                    const float* __restrict__ ln1w,
                                                    const float* __restrict__ ln1b,
                                                    const float* __restrict__ ln2w,
                                                    const float* __restrict__ ln2b,
                                                    float* __restrict__ out) {
    int n = blockIdx.x;
    int tid = threadIdx.x;
    __shared__ float sW[3072];
    __shared__ float sww[512];
    __shared__ float sx[3][512];
    __shared__ float sxa[256];
    __shared__ float sg[512];
    __shared__ float sw2[512];
    __shared__ float semb[64];
    __shared__ float sbias[64];
    __shared__ float smu[16], srs[16], smu2[16], srs2[16];

    for (int u = tid; u < 448; u += 128) {
        uint4 v = *(const uint4*)&g_W16[(size_t)n * 3584 + u * 8];
        const __half* h = (const __half*)&v;
        int base = u * 8;
        if (base < 3072) {
            #pragma unroll
            for (int p = 0; p < 8; p++) sW[base + p] = __half2float(h[p]);
        } else {
            #pragma unroll
            for (int p = 0; p < 8; p++) sww[base - 3072 + p] = __half2float(h[p]);
        }
    }
    {
        int b = tid >> 3, i4 = (tid & 7) * 4;
        *(float4*)&sx[0][tid * 4] = *(const float4*)&x[((size_t)b * Nn + n) * 32 + i4];
    }
    *(float4*)&sx[1][tid * 4] = *(const float4*)&g_y1[(size_t)n * 512 + tid * 4];
    *(float4*)&sx[2][tid * 4] = *(const float4*)&g_y2[(size_t)n * 512 + tid * 4];
    if (tid < 64) {
        *(float4*)&sxa[tid * 4] = *(const float4*)&g_xwagg[(size_t)n * 256 + tid * 4];
        semb[tid] = emb[(size_t)n * 64 + tid];
    }
    __syncthreads();

    #pragma unroll
    for (int q = 0; q < 4; q++) {
        int s = tid + 128 * q;
        int b = s >> 5, o = s & 31;
        float a = 0.0f;
        #pragma unroll
        for (int k = 0; k < 3; k++)
            #pragma unroll
            for (int i = 0; i < 32; i++)
                a = fmaf(sx[k][b * 32 + i], sW[k * 1024 + i * 32 + o], a);
        sg[s] = a;
        float w = 0.0f;
        #pragma unroll
        for (int i = 0; i < 16; i++)
            w = fmaf(sxa[b * 16 + i], sww[i * 32 + o], w);
        sw2[s] = w;
    }
    if (tid < 64) {
        float bsum = 0.0f;
        #pragma unroll
        for (int d = 0; d < 64; d++)
            bsum = fmaf(semb[d], __ldg(&bpool[d * 64 + tid]), bsum);
        sbias[tid] = bsum;
    }
    __syncthreads();

    if (tid < 16) {
        float s1 = 0, q1 = 0, s2 = 0, q2 = 0;
        #pragma unroll
        for (int o = 0; o < 32; o++) {
            float v = sg[tid * 32 + o];
            s1 += v; q1 = fmaf(v, v, q1);
            float u = sw2[tid * 32 + o];
            s2 += u; q2 = fmaf(u, u, q2);
        }
        float mu1 = s1 * (1.0f / 32.0f), mu2 = s2 * (1.0f / 32.0f);
        smu[tid] = mu1;
        srs[tid] = rsqrtf(fmaxf(q1 * (1.0f / 32.0f) - mu1 * mu1, 0.0f) + 1e-5f);
        smu2[tid] = mu2;
        srs2[tid] = rsqrtf(fmaxf(q2 * (1.0f / 32.0f) - mu2 * mu2, 0.0f) + 1e-5f);
    }
    __syncthreads();

    #pragma unroll
    for (int q = 0; q < 8; q++) {
        int s = tid + 128 * q;
        int b = s >> 6, h = s & 63;
        float v;
        if (h < 32)
            v = (sg[b * 32 + h] - smu[b]) * srs[b] * __ldg(&ln1w[h]) + __ldg(&ln1b[h]);
        else
            v = (sw2[b * 32 + h - 32] - smu2[b]) * srs2[b] * __ldg(&ln2w[h - 32]) + __ldg(&ln2b[h - 32]);
        out[((size_t)b * Nn + n) * 64 + h] = v + sbias[h];
    }
}

extern "C" void kernel_launch(void* const* d_in, const int* in_sizes, int n_in,
                              void* d_out, int out_size) {
    const float* x    = (const float*)d_in[0];
    const float* xw   = (const float*)d_in[1];
    const float* emb  = (const float*)d_in[2];
    const float* wp   = (const float*)d_in[3];
    const float* wwin = (const float*)d_in[4];
    const float* bp   = (const float*)d_in[5];
    const float* T    = (const float*)d_in[6];
    const float* l1w  = (const float*)d_in[7];
    const float* l1b  = (const float*)d_in[8];
    const float* l2w  = (const float*)d_in[9];
    const float* l2b  = (const float*)d_in[10];
    float* out = (float*)d_out;

    cudaFuncSetAttribute(pexp_tc, cudaFuncAttributeMaxDynamicSharedMemorySize, PE_SMEM);
    cudaFuncSetAttribute(tc_gemm, cudaFuncAttributeMaxDynamicSharedMemorySize, SMEM_BYTES);

    prep_kernel<<<666, 256>>>(x, emb, wp, wwin);             // 0
    rowmax_tc<<<dim3(2, 40), 256>>>();                       // 1
    pexp_tc<<<dim3(2, 40), 256, PE_SMEM>>>();                // 2  (80 CTAs, one wave)
    tc_gemm<<<dim3(4, 32), 512, SMEM_BYTES>>>(0);            // 3  <- profiled slot
    tc_gemm<<<dim3(4, 32), 512, SMEM_BYTES>>>(1);            // 4
    pool_tc<<<dim3(28, 40), 256>>>();                        // 5
    xwagg_kernel<<<(Nn * Bb * 16 + 255) / 256, 256>>>(xw, T);// 6
    final_kernel<<<Nn, 128>>>(x, emb, bp, l1w, l1b, l2w, l2b, out); // 7
}

// round 15
// speedup vs baseline: 1.0038x; 1.0038x over previous
#include <cuda_runtime.h>
#include <cuda_fp16.h>
#include <cstdint>

#define Nn   5000
#define Bb   16
#define MP   5120          // padded node dim, 40*128 = 32*160
#define NK   80            // MP/64 k-chunks

// ---------------- scratch (device globals, zero-initialized at load) ----------------
__device__ __half g_Eh[(size_t)MP * 64];
__device__ __half g_El[(size_t)MP * 64];
__device__ float g_rowmax[MP];
__device__ float g_rsp[2][MP];
__device__ __half g_Ph[(size_t)MP * MP];
__device__ __half g_xT_h[(size_t)512 * MP];
__device__ __half g_y1T_h[(size_t)512 * MP];
__device__ float g_y1[(size_t)Nn * 512];
__device__ float g_y2[(size_t)Nn * 512];
__device__ __half g_WT[(size_t)3584 * 64];
__device__ __half g_W16[(size_t)MP * 3584];
__device__ float g_xwagg[Nn * Bb * 16];

// ---------------- base-ISA tensor helpers ----------------
__device__ __forceinline__ void cpa16(uint32_t s, const void* g) {
    asm volatile("cp.async.cg.shared.global [%0], [%1], 16;" :: "r"(s), "l"(g) : "memory");
}
__device__ __forceinline__ void ldsm4(uint32_t* r, uint32_t a) {
    asm volatile("ldmatrix.sync.aligned.m8n8.x4.shared.b16 {%0,%1,%2,%3}, [%4];"
                 : "=r"(r[0]), "=r"(r[1]), "=r"(r[2]), "=r"(r[3]) : "r"(a));
}
__device__ __forceinline__ void ldsm2(uint32_t* r, uint32_t a) {
    asm volatile("ldmatrix.sync.aligned.m8n8.x2.shared.b16 {%0,%1}, [%2];"
                 : "=r"(r[0]), "=r"(r[1]) : "r"(a));
}
__device__ __forceinline__ void mma_h(float* d, const uint32_t* a, const uint32_t* b) {
    asm volatile("mma.sync.aligned.m16n8k16.row.col.f32.f16.f16.f32 "
                 "{%0,%1,%2,%3}, {%4,%5,%6,%7}, {%8,%9}, {%0,%1,%2,%3};"
                 : "+f"(d[0]), "+f"(d[1]), "+f"(d[2]), "+f"(d[3])
                 : "r"(a[0]), "r"(a[1]), "r"(a[2]), "r"(a[3]), "r"(b[0]), "r"(b[1]));
}
__device__ __forceinline__ uint32_t pack2h(float a, float b) {
    __half2 h = __halves2half2(__float2half_rn(a), __float2half_rn(b));
    return *(uint32_t*)&h;
}
__device__ __forceinline__ uint32_t smem_u32(const void* p) {
    uint32_t r;
    asm("{ .reg .u64 t; cvta.to.shared.u64 t, %1; cvt.u32.u64 %0, t; }" : "=r"(r) : "l"(p));
    return r;
}

// ---------------- prep ----------------
__global__ void prep_kernel(const float* __restrict__ x, const float* __restrict__ emb,
                            const float* __restrict__ wp, const float* __restrict__ wwin) {
    __shared__ float t[64][65];
    if (blockIdx.x < 632) {
        int mt = blockIdx.x % 79, jt = blockIdx.x / 79;
        int m0 = mt * 64, j0 = jt * 64;
        #pragma unroll
        for (int q = 0; q < 16; q++) {
            int f = threadIdx.x + 256 * q;
            int mr = f >> 6, jj = f & 63;
            int m = m0 + mr, j = j0 + jj;
            float v = (m < Nn) ? x[(((size_t)(j >> 5)) * Nn + m) * 32 + (j & 31)] : 0.0f;
            t[jj][mr] = v;
        }
        __syncthreads();
        #pragma unroll
        for (int q = 0; q < 16; q++) {
            int f = threadIdx.x + 256 * q;
            int jj = f >> 6, mr = f & 63;
            int m = m0 + mr;
            if (m < Nn)
                g_xT_h[(size_t)(j0 + jj) * MP + m] = __float2half_rn(t[jj][mr]);
        }
    } else if (blockIdx.x < 652) {
        int gid = (blockIdx.x - 632) * 256 + threadIdx.x;
        for (int i = gid; i < Nn * 64; i += 20 * 256) {
            float v = emb[i];
            __half h = __float2half_rn(v);
            g_Eh[i] = h;
            g_El[i] = __float2half_rn(v - __half2float(h));
        }
    } else {
        int j = (blockIdx.x - 652) * 256 + threadIdx.x;
        #pragma unroll 8
        for (int d = 0; d < 64; d++) {
            float v = (j < 3072) ? wp[(size_t)d * 3072 + j]
                                 : wwin[(size_t)d * 512 + (j - 3072)];
            g_WT[(size_t)j * 64 + d] = __float2half_rn(v);
        }
    }
}

// ---------------- rowmax ----------------
__global__ void __launch_bounds__(256) rowmax_tc() {
    __shared__ __align__(16) char sm[33280];
    uint32_t raw = smem_u32(sm);
    uint32_t SAH = raw, SBH = raw + 16384;
    unsigned* smax = (unsigned*)(sm + 32768);
    int tid = threadIdx.x, lane = tid & 31, wid = tid >> 5;
    int wm = wid >> 2, wn = wid & 3;
    int m0 = blockIdx.y * 128, nb = blockIdx.x * 2560;

    #pragma unroll
    for (int q = 0; q < 4; q++) {
        int u = tid + 256 * q;
        int row = u >> 3, c16 = u & 7;
        uint4 v = *(const uint4*)(g_Eh + (size_t)(m0 + row) * 64 + c16 * 8);
        *(uint4*)(sm + (row * 128 + ((c16 ^ (row & 7)) * 16))) = v;
    }
    if (tid < 128) smax[tid] = 0u;
    __syncthreads();

    int hb = lane >> 4, bbit = (lane >> 3) & 1;
    uint32_t a_off[4], a7[4], b_off[4], b7[4];
    #pragma unroll
    for (int mf = 0; mf < 4; mf++) {
        int ar = wm * 64 + mf * 16 + (lane & 15);
        a_off[mf] = (uint32_t)(ar * 128); a7[mf] = (uint32_t)(ar & 7);
    }
    #pragma unroll
    for (int nf = 0; nf < 4; nf++) {
        int br = wn * 32 + nf * 8 + (lane & 7);
        b_off[nf] = (uint32_t)(br * 128); b7[nf] = (uint32_t)(br & 7);
    }

    float rmx[4][2];
    #pragma unroll
    for (int mf = 0; mf < 4; mf++) { rmx[mf][0] = 0.0f; rmx[mf][1] = 0.0f; }

    for (int sub = 0; sub < 20; sub++) {
        int n0 = nb + sub * 128;
        #pragma unroll
        for (int q = 0; q < 4; q++) {
            int u = tid + 256 * q;
            int row = u >> 3, c16 = u & 7;
            uint4 v = *(const uint4*)(g_Eh + (size_t)(n0 + row) * 64 + c16 * 8);
            *(uint4*)(sm + 16384 + (row * 128 + ((c16 ^ (row & 7)) * 16))) = v;
        }
        __syncthreads();
        float acc[4][4][4];
        #pragma unroll
        for (int mf = 0; mf < 4; mf++)
            #pragma unroll
            for (int nf = 0; nf < 4; nf++)
                #pragma unroll
                for (int e = 0; e < 4; e++) acc[mf][nf][e] = 0.0f;
        #pragma unroll
        for (int ks = 0; ks < 4; ks++) {
            uint32_t af[4][4], bfx[4][2];
            uint32_t ca = (uint32_t)(ks * 2 + hb), cb = (uint32_t)(ks * 2 + bbit);
            #pragma unroll
            for (int mf = 0; mf < 4; mf++) ldsm4(af[mf], SAH + a_off[mf] + ((ca ^ a7[mf]) << 4));
            #pragma unroll
            for (int nf = 0; nf < 4; nf++) ldsm2(bfx[nf], SBH + b_off[nf] + ((cb ^ b7[nf]) << 4));
            #pragma unroll
            for (int mf = 0; mf < 4; mf++)
                #pragma unroll
                for (int nf = 0; nf < 4; nf++) mma_h(acc[mf][nf], af[mf], bfx[nf]);
        }
        #pragma unroll
        for (int mf = 0; mf < 4; mf++)
            #pragma unroll
            for (int nf = 0; nf < 4; nf++) {
                rmx[mf][0] = fmaxf(rmx[mf][0], fmaxf(acc[mf][nf][0], acc[mf][nf][1]));
                rmx[mf][1] = fmaxf(rmx[mf][1], fmaxf(acc[mf][nf][2], acc[mf][nf][3]));
            }
        __syncthreads();
    }
    int g = lane >> 2;
    #pragma unroll
    for (int mf = 0; mf < 4; mf++) {
        int r1 = wm * 64 + mf * 16 + g;
        atomicMax(&smax[r1], __float_as_uint(rmx[mf][0]));
        atomicMax(&smax[r1 + 8], __float_as_uint(rmx[mf][1]));
    }
    __syncthreads();
    if (tid < 128) atomicMax((unsigned*)&g_rowmax[m0 + tid], smax[tid]);
}

// ---------------- pexp: 80 CTAs (one wave), 20 subs each ----------------
#define PE_SMEM 101376
__global__ void __launch_bounds__(256) pexp_tc() {
    extern __shared__ char sm[];
    uint32_t raw = smem_u32(sm);
    uint32_t SAH = raw, SAL = raw + 16384, SBH = raw + 32768, SBL = raw + 49152;
    float* stg   = (float*)(sm + 32768);
    float* rsum  = (float*)(sm + 100352);
    float* rmaxS = (float*)(sm + 100864);

    int tid = threadIdx.x, lane = tid & 31, wid = tid >> 5;
    int wm = wid >> 2, wn = wid & 3;
    int m0 = blockIdx.y * 128, nc0 = blockIdx.x * 2560;

    #pragma unroll
    for (int q = 0; q < 8; q++) {
        int id = tid + 256 * q;
        int hf = id >> 10, u = id & 1023;
        int row = u >> 3, c16 = u & 7;
        const __half* src = hf ? g_El : g_Eh;
        uint4 v = *(const uint4*)(src + (size_t)(m0 + row) * 64 + c16 * 8);
        *(uint4*)(sm + (hf ? 16384 : 0) + row * 128 + ((c16 ^ (row & 7)) * 16)) = v;
    }
    if (tid < 128) { rsum[tid] = 0.0f; rmaxS[tid] = g_rowmax[m0 + tid]; }
    __syncthreads();

    int hb = lane >> 4, bbit = (lane >> 3) & 1;
    uint32_t a_off[4], a7[4], b_off[4], b7[4];
    #pragma unroll
    for (int mf = 0; mf < 4; mf++) {
        int ar = wm * 64 + mf * 16 + (lane & 15);
        a_off[mf] = (uint32_t)(ar * 128); a7[mf] = (uint32_t)(ar & 7);
    }
    #pragma unroll
    for (int nf = 0; nf < 4; nf++) {
        int br = wn * 32 + nf * 8 + (lane & 7);
        b_off[nf] = (uint32_t)(br * 128); b7[nf] = (uint32_t)(br & 7);
    }

    for (int sub = 0; sub < 20; sub++) {
        int n0 = nc0 + sub * 128;
        #pragma unroll
        for (int q = 0; q < 8; q++) {
            int id = tid + 256 * q;
            int hf = id >> 10, u = id & 1023;
            int row = u >> 3, c16 = u & 7;
            const __half* src = hf ? g_El : g_Eh;
            uint4 v = *(const uint4*)(src + (size_t)(n0 + row) * 64 + c16 * 8);
            *(uint4*)(sm + (hf ? 49152 : 32768) + row * 128 + ((c16 ^ (row & 7)) * 16)) = v;
        }
        __syncthreads();

        float acc[4][4][4];
        #pragma unroll
        for (int mf = 0; mf < 4; mf++)
            #pragma unroll
            for (int nf = 0; nf < 4; nf++)
                #pragma unroll
                for (int e = 0; e < 4; e++) acc[mf][nf][e] = 0.0f;
        #pragma unroll
        for (int ks = 0; ks < 4; ks++) {
            uint32_t ah[4][4], al[4][4], bh[4][2], bl[4][2];
            uint32_t ca = (uint32_t)(ks * 2 + hb), cb = (uint32_t)(ks * 2 + bbit);
            #pragma unroll
            for (int mf = 0; mf < 4; mf++) {
                uint32_t xo = a_off[mf] + ((ca ^ a7[mf]) << 4);
                ldsm4(ah[mf], SAH + xo);
                ldsm4(al[mf], SAL + xo);
            }
            #pragma unroll
            for (int nf = 0; nf < 4; nf++) {
                uint32_t xo = b_off[nf] + ((cb ^ b7[nf]) << 4);
                ldsm2(bh[nf], SBH + xo);
                ldsm2(bl[nf], SBL + xo);
            }
            #pragma unroll
            for (int mf = 0; mf < 4; mf++)
                #pragma unroll
                for (int nf = 0; nf < 4; nf++) {
                    mma_h(acc[mf][nf], ah[mf], bh[nf]);
                    mma_h(acc[mf][nf], ah[mf], bl[nf]);
                    mma_h(acc[mf][nf], al[mf], bh[nf]);
                }
        }
        __syncthreads();

        int g = lane >> 2, t4 = lane & 3;
        #pragma unroll
        for (int mf = 0; mf < 4; mf++) {
            int r1 = wm * 64 + mf * 16 + g, r2 = r1 + 8;
            float mx1 = rmaxS[r1], mx2 = rmaxS[r2];
            #pragma unroll
            for (int nf = 0; nf < 4; nf++) {
                int c = wn * 32 + nf * 8 + t4 * 2;
                stg[r1 * 132 + c]     = __expf(fmaxf(acc[mf][nf][0], 0.0f) - mx1);
                stg[r1 * 132 + c + 1] = __expf(fmaxf(acc[mf][nf][1], 0.0f) - mx1);
                stg[r2 * 132 + c]     = __expf(fmaxf(acc[mf][nf][2], 0.0f) - mx2);
                stg[r2 * 132 + c + 1] = __expf(fmaxf(acc[mf][nf][3], 0.0f) - mx2);
            }
        }
        __syncthreads();

        if (tid < 128) {
            float s = 0.0f;
            #pragma unroll 8
            for (int c = 0; c < 128; c++) s += stg[tid * 132 + c];
            rsum[tid] += s;
        }
        #pragma unroll
        for (int q = 0; q < 8; q++) {
            int id = tid + 256 * q;
            int row = id >> 4, cu = id & 15;
            uint32_t wh[4];
            #pragma unroll
            for (int p = 0; p < 4; p++)
                wh[p] = pack2h(stg[row * 132 + cu * 8 + 2 * p],
                               stg[row * 132 + cu * 8 + 2 * p + 1]);
            *(uint4*)(g_Ph + (size_t)(m0 + row) * MP + n0 + cu * 8) =
                make_uint4(wh[0], wh[1], wh[2], wh[3]);
        }
        __syncthreads();
    }
    if (tid < 128) g_rsp[blockIdx.x][m0 + tid] = rsum[tid];
}

// ---------------- HMMA GEMM: split-k dual groups, cross-iter fragment pipeline ----------------
#define MT 160
#define JT 128
#define ABYTES 20480
#define BBYTES 16384
#define GSTG   (ABYTES + BBYTES)          // 36864 per stage
#define SMEM_BYTES (1024 + 6 * GSTG)      // 222208
#define SST 132

__global__ void __launch_bounds__(512, 1) tc_gemm(int which) {
    extern __shared__ char dsm[];
    uint32_t raw = smem_u32(dsm);
    uint32_t sb = (raw + 1023u) & ~1023u;

    int tid = threadIdx.x, lane = tid & 31, wid = tid >> 5;
    int grp = wid >> 3;
    int wg  = wid & 7;
    int wm = wg >> 2, wn = wg & 3;
    int gtid = tid & 255;
    int m0 = blockIdx.y * MT, j0 = blockIdx.x * JT;

    const __half* __restrict__ BT = which ? g_y1T_h : g_xT_h;

    uint32_t sA[5], sB[4];
    size_t gA[5], gB[4];
    #pragma unroll
    for (int q = 0; q < 5; q++) {
        int u = gtid + 256 * q;
        int row = u >> 3, c16 = u & 7;
        sA[q] = (uint32_t)(row * 128 + ((c16 ^ (row & 7)) * 16));
        gA[q] = (size_t)(m0 + row) * MP + c16 * 8;
    }
    #pragma unroll
    for (int q = 0; q < 4; q++) {
        int u = gtid + 256 * q;
        int row = u >> 3, c16 = u & 7;
        sB[q] = (uint32_t)(row * 128 + ((c16 ^ (row & 7)) * 16));
        gB[q] = (size_t)(j0 + row) * MP + c16 * 8;
    }

    // group g handles chunks t = 2l+g, stage = grp*3 + l%3
    auto issueg = [&](int l) {
        uint32_t base = sb + (uint32_t)(grp * 3 + l % 3) * GSTG;
        size_t ko = (size_t)(2 * l + grp) * 64;
        #pragma unroll
        for (int q = 0; q < 5; q++) cpa16(base + sA[q], g_Ph + gA[q] + ko);
        #pragma unroll
        for (int q = 0; q < 4; q++) cpa16(base + ABYTES + sB[q], BT + gB[q] + ko);
        asm volatile("cp.async.commit_group;" ::: "memory");
    };

    uint32_t a_off[5], a7[5], b_off[4], b7[4];
    int hb = lane >> 4, bbit = (lane >> 3) & 1;
    #pragma unroll
    for (int mf = 0; mf < 5; mf++) {
        int ar = wm * 80 + mf * 16 + (lane & 15);
        a_off[mf] = (uint32_t)(ar * 128); a7[mf] = (uint32_t)(ar & 7);
    }
    #pragma unroll
    for (int nf = 0; nf < 4; nf++) {
        int br = wn * 32 + nf * 8 + (lane & 7);
        b_off[nf] = (uint32_t)(br * 128); b7[nf] = (uint32_t)(br & 7);
    }

    float acc[5][4][4];
    #pragma unroll
    for (int mf = 0; mf < 5; mf++)
        #pragma unroll
        for (int nf = 0; nf < 4; nf++)
            #pragma unroll
            for (int e = 0; e < 4; e++) acc[mf][nf][e] = 0.0f;

    uint32_t af[2][5][4], bfr[2][4][2];

    // prologue: fill 3 stages, wait for first two, group barrier, prime ks0
    issueg(0); issueg(1); issueg(2);
    asm volatile("cp.async.wait_group 1;" ::: "memory");
    asm volatile("bar.sync %0, %1;" :: "r"(grp + 1), "r"(256) : "memory");
    {
        uint32_t Abuf = sb + (uint32_t)(grp * 3) * GSTG;
        uint32_t Bbuf = Abuf + ABYTES;
        uint32_t ca = (uint32_t)hb, cb = (uint32_t)bbit;
        #pragma unroll
        for (int mf = 0; mf < 5; mf++) ldsm4(af[0][mf], Abuf + a_off[mf] + ((ca ^ a7[mf]) << 4));
        #pragma unroll
        for (int nf = 0; nf < 4; nf++) ldsm2(bfr[0][nf], Bbuf + b_off[nf] + ((cb ^ b7[nf]) << 4));
    }

    for (int l = 0; l < 40; l++) {
        uint32_t Abuf = sb + (uint32_t)(grp * 3 + l % 3) * GSTG;
        uint32_t Bbuf = Abuf + ABYTES;
        uint32_t AbufN = sb + (uint32_t)(grp * 3 + (l + 1) % 3) * GSTG;
        uint32_t BbufN = AbufN + ABYTES;

        #pragma unroll
        for (int ks = 0; ks < 4; ks++) {
            int cur = ks & 1, nxt = cur ^ 1;
            if (ks < 3) {
                uint32_t ca = (uint32_t)((ks + 1) * 2 + hb), cb = (uint32_t)((ks + 1) * 2 + bbit);
                #pragma unroll
                for (int mf = 0; mf < 5; mf++) ldsm4(af[nxt][mf], Abuf + a_off[mf] + ((ca ^ a7[mf]) << 4));
                #pragma unroll
                for (int nf = 0; nf < 4; nf++) ldsm2(bfr[nxt][nf], Bbuf + b_off[nf] + ((cb ^ b7[nf]) << 4));
            } else if (l + 1 < 40) {
                // cross-iteration prefetch: next chunk's ks=0 from its (already-complete) stage
                uint32_t ca = (uint32_t)hb, cb = (uint32_t)bbit;
                #pragma unroll
                for (int mf = 0; mf < 5; mf++) ldsm4(af[nxt][mf], AbufN + a_off[mf] + ((ca ^ a7[mf]) << 4));
                #pragma unroll
                for (int nf = 0; nf < 4; nf++) ldsm2(bfr[nxt][nf], BbufN + b_off[nf] + ((cb ^ b7[nf]) << 4));
            }
            #pragma unroll
            for (int mf = 0; mf < 5; mf++)
                #pragma unroll
                for (int nf = 0; nf < 4; nf++)
                    mma_h(acc[mf][nf], af[cur][mf], bfr[cur][nf]);
        }
        // tail: wait (own groups) -> barrier (visibility + overwrite safety) -> issue
        if (l + 1 < 40) {
            asm volatile("cp.async.wait_group 1;" ::: "memory");
            asm volatile("bar.sync %0, %1;" :: "r"(grp + 1), "r"(256) : "memory");
            if (l + 3 < 40) issueg(l + 3);
        }
    }
    asm volatile("cp.async.wait_group 0;" ::: "memory");
    __syncthreads();   // both groups done; all async drained before smem reuse

    // ---- cross-group reduction + scale + writeout ----
    float* st = (float*)(dsm + (sb - raw));
    int g = lane >> 2, t4 = lane & 3;

    if (grp == 1) {
        #pragma unroll
        for (int mf = 0; mf < 5; mf++) {
            int r0 = wm * 80 + mf * 16 + g;
            #pragma unroll
            for (int nf = 0; nf < 4; nf++) {
                int c0 = wn * 32 + nf * 8 + t4 * 2;
                st[r0 * SST + c0]           = acc[mf][nf][0];
                st[r0 * SST + c0 + 1]       = acc[mf][nf][1];
                st[(r0 + 8) * SST + c0]     = acc[mf][nf][2];
                st[(r0 + 8) * SST + c0 + 1] = acc[mf][nf][3];
            }
        }
    }
    __syncthreads();
    if (grp == 0) {
        #pragma unroll
        for (int mf = 0; mf < 5; mf++) {
            int r0 = wm * 80 + mf * 16 + g;
            int ma = m0 + r0, mb = ma + 8;
            float al0 = 0.0f, al1 = 0.0f;
            if (ma < Nn) al0 = 1.0f / (g_rsp[0][ma] + g_rsp[1][ma]);
            if (mb < Nn) al1 = 1.0f / (g_rsp[0][mb] + g_rsp[1][mb]);
            #pragma unroll
            for (int nf = 0; nf < 4; nf++) {
                int c0 = wn * 32 + nf * 8 + t4 * 2;
                st[r0 * SST + c0]           = (acc[mf][nf][0] + st[r0 * SST + c0]) * al0;
                st[r0 * SST + c0 + 1]       = (acc[mf][nf][1] + st[r0 * SST + c0 + 1]) * al0;
                st[(r0 + 8) * SST + c0]     = (acc[mf][nf][2] + st[(r0 + 8) * SST + c0]) * al1;
                st[(r0 + 8) * SST + c0 + 1] = (acc[mf][nf][3] + st[(r0 + 8) * SST + c0 + 1]) * al1;
            }
        }
    }
    __syncthreads();

    float* __restrict__ Y = which ? g_y2 : g_y1;
    for (int u = tid; u < MT * 32; u += 512) {
        int r = u >> 5, ch = u & 31;
        int m = m0 + r;
        if (m < Nn) {
            float4 v = {st[r * SST + ch * 4],     st[r * SST + ch * 4 + 1],
                        st[r * SST + ch * 4 + 2], st[r * SST + ch * 4 + 3]};
            *(float4*)&Y[(size_t)m * 512 + j0 + ch * 4] = v;
        }
    }
    if (which == 0) {
        for (int u = tid; u < JT * 20; u += 512) {
            int j = u / 20, mm = u % 20;
            uint32_t w[4];
            #pragma unroll
            for (int p = 0; p < 4; p++)
                w[p] = pack2h(st[(mm * 8 + 2 * p) * SST + j],
                              st[(mm * 8 + 2 * p + 1) * SST + j]);
            *(uint4*)&g_y1T_h[(size_t)(j0 + j) * MP + m0 + mm * 8] =
                make_uint4(w[0], w[1], w[2], w[3]);
        }
    }
}

// ---------------- pool_tc ----------------
__global__ void __launch_bounds__(256) pool_tc() {
    __shared__ __align__(16) char sm[49152];
    uint32_t raw = smem_u32(sm);
    uint32_t SAH = raw, SAL = raw + 16384, SBH = raw + 32768;
    int tid = threadIdx.x, lane = tid & 31, wid = tid >> 5;
    int wm = wid >> 2, wn = wid & 3;
    int m0 = blockIdx.y * 128, j0 = blockIdx.x * 128;

    #pragma unroll
    for (int q = 0; q < 4; q++) {
        int u = tid + 256 * q;
        int row = u >> 3, c16 = u & 7;
        uint32_t so = (uint32_t)(row * 128 + ((c16 ^ (row & 7)) * 16));
        *(uint4*)(sm + so)          = *(const uint4*)(g_Eh + (size_t)(m0 + row) * 64 + c16 * 8);
        *(uint4*)(sm + 16384 + so)  = *(const uint4*)(g_El + (size_t)(m0 + row) * 64 + c16 * 8);
        *(uint4*)(sm + 32768 + so)  = *(const uint4*)(g_WT + (size_t)(j0 + row) * 64 + c16 * 8);
    }
    __syncthreads();

    int hb = lane >> 4, bbit = (lane >> 3) & 1;
    uint32_t a_off[4], a7[4], b_off[4], b7[4];
    #pragma unroll
    for (int mf = 0; mf < 4; mf++) {
        int ar = wm * 64 + mf * 16 + (lane & 15);
        a_off[mf] = (uint32_t)(ar * 128); a7[mf] = (uint32_t)(ar & 7);
    }
    #pragma unroll
    for (int nf = 0; nf < 4; nf++) {
        int br = wn * 32 + nf * 8 + (lane & 7);
        b_off[nf] = (uint32_t)(br * 128); b7[nf] = (uint32_t)(br & 7);
    }

    float acc[4][4][4];
    #pragma unroll
    for (int mf = 0; mf < 4; mf++)
        #pragma unroll
        for (int nf = 0; nf < 4; nf++)
            #pragma unroll
            for (int e = 0; e < 4; e++) acc[mf][nf][e] = 0.0f;

    #pragma unroll
    for (int ks = 0; ks < 4; ks++) {
        uint32_t ah[4][4], al[4][4], bh[4][2];
        uint32_t ca = (uint32_t)(ks * 2 + hb), cb = (uint32_t)(ks * 2 + bbit);
        #pragma unroll
        for (int mf = 0; mf < 4; mf++) {
            uint32_t xo = a_off[mf] + ((ca ^ a7[mf]) << 4);
            ldsm4(ah[mf], SAH + xo);
            ldsm4(al[mf], SAL + xo);
        }
        #pragma unroll
        for (int nf = 0; nf < 4; nf++) ldsm2(bh[nf], SBH + b_off[nf] + ((cb ^ b7[nf]) << 4));
        #pragma unroll
        for (int mf = 0; mf < 4; mf++)
            #pragma unroll
            for (int nf = 0; nf < 4; nf++) {
                mma_h(acc[mf][nf], ah[mf], bh[nf]);
                mma_h(acc[mf][nf], al[mf], bh[nf]);
            }
    }

    int g = lane >> 2, t4 = lane & 3;
    #pragma unroll
    for (int mf = 0; mf < 4; mf++) {
        int r1 = m0 + wm * 64 + mf * 16 + g;
        #pragma unroll
        for (int nf = 0; nf < 4; nf++) {
            int c = j0 + wn * 32 + nf * 8 + t4 * 2;
            *(uint32_t*)&g_W16[(size_t)r1 * 3584 + c] = pack2h(acc[mf][nf][0], acc[mf][nf][1]);
            *(uint32_t*)&g_W16[(size_t)(r1 + 8) * 3584 + c] = pack2h(acc[mf][nf][2], acc[mf][nf][3]);
        }
    }
}

// ---------------- xwagg ----------------
__global__ void xwagg_kernel(const float* __restrict__ xw, const float* __restrict__ T) {
    int idx = blockIdx.x * 256 + threadIdx.x;
    if (idx >= Nn * Bb * 16) return;
    int n = idx >> 8, r = idx & 255, b = r >> 4, i = r & 15;
    float s = 0.0f;
    #pragma unroll
    for (int t = 0; t < 12; t++)
        s = fmaf(__ldg(&T[t]), xw[(((size_t)b * 12 + t) * Nn + n) * 16 + i], s);
    g_xwagg[idx] = s;
}

// ---------------- fused epilogue ----------------
__global__ void __launch_bounds__(128) final_kernel(const float* __restrict__ x,
                                                    const float* __restrict__ emb,
                                                    const float* __restrict__ bpool,
                                                    const float* __restrict__ ln1w,
                                                    const float* __restrict__ ln1b,
                                                    const float* __restrict__ ln2w,
                                                    const float* __restrict__ ln2b,
                                                    float* __restrict__ out) {
    int n = blockIdx.x;
    int tid = threadIdx.x;
    __shared__ float sW[3072];
    __shared__ float sww[512];
    __shared__ float sx[3][512];
    __shared__ float sxa[256];
    __shared__ float sg[512];
    __shared__ float sw2[512];
    __shared__ float semb[64];
    __shared__ float sbias[64];
    __shared__ float smu[16], srs[16], smu2[16], srs2[16];

    for (int u = tid; u < 448; u += 128) {
        uint4 v = *(const uint4*)&g_W16[(size_t)n * 3584 + u * 8];
        const __half* h = (const __half*)&v;
        int base = u * 8;
        if (base < 3072) {
            #pragma unroll
            for (int p = 0; p < 8; p++) sW[base + p] = __half2float(h[p]);
        } else {
            #pragma unroll
            for (int p = 0; p < 8; p++) sww[base - 3072 + p] = __half2float(h[p]);
        }
    }
    {
        int b = tid >> 3, i4 = (tid & 7) * 4;
        *(float4*)&sx[0][tid * 4] = *(const float4*)&x[((size_t)b * Nn + n) * 32 + i4];
    }
    *(float4*)&sx[1][tid * 4] = *(const float4*)&g_y1[(size_t)n * 512 + tid * 4];
    *(float4*)&sx[2][tid * 4] = *(const float4*)&g_y2[(size_t)n * 512 + tid * 4];
    if (tid < 64) {
        *(float4*)&sxa[tid * 4] = *(const float4*)&g_xwagg[(size_t)n * 256 + tid * 4];
        semb[tid] = emb[(size_t)n * 64 + tid];
    }
    __syncthreads();

    #pragma unroll
    for (int q = 0; q < 4; q++) {
        int s = tid + 128 * q;
        int b = s >> 5, o = s & 31;
        float a = 0.0f;
        #pragma unroll
        for (int k = 0; k < 3; k++)
            #pragma unroll
            for (int i = 0; i < 32; i++)
                a = fmaf(sx[k][b * 32 + i], sW[k * 1024 + i * 32 + o], a);
        sg[s] = a;
        float w = 0.0f;
        #pragma unroll
        for (int i = 0; i < 16; i++)
            w = fmaf(sxa[b * 16 + i], sww[i * 32 + o], w);
        sw2[s] = w;
    }
    if (tid < 64) {
        float bsum = 0.0f;
        #pragma unroll
        for (int d = 0; d < 64; d++)
            bsum = fmaf(semb[d], __ldg(&bpool[d * 64 + tid]), bsum);
        sbias[tid] = bsum;
    }
    __syncthreads();

    if (tid < 16) {
        float s1 = 0, q1 = 0, s2 = 0, q2 = 0;
        #pragma unroll
        for (int o = 0; o < 32; o++) {
            float v = sg[tid * 32 + o];
            s1 += v; q1 = fmaf(v, v, q1);
            float u = sw2[tid * 32 + o];
            s2 += u; q2 = fmaf(u, u, q2);
        }
        float mu1 = s1 * (1.0f / 32.0f), mu2 = s2 * (1.0f / 32.0f);
        smu[tid] = mu1;
        srs[tid] = rsqrtf(fmaxf(q1 * (1.0f / 32.0f) - mu1 * mu1, 0.0f) + 1e-5f);
        smu2[tid] = mu2;
        srs2[tid] = rsqrtf(fmaxf(q2 * (1.0f / 32.0f) - mu2 * mu2, 0.0f) + 1e-5f);
    }
    __syncthreads();

    #pragma unroll
    for (int q = 0; q < 8; q++) {
        int s = tid + 128 * q;
        int b = s >> 6, h = s & 63;
        float v;
        if (h < 32)
            v = (sg[b * 32 + h] - smu[b]) * srs[b] * __ldg(&ln1w[h]) + __ldg(&ln1b[h]);
        else
            v = (sw2[b * 32 + h - 32] - smu2[b]) * srs2[b] * __ldg(&ln2w[h - 32]) + __ldg(&ln2b[h - 32]);
        out[((size_t)b * Nn + n) * 64 + h] = v + sbias[h];
    }
}

extern "C" void kernel_launch(void* const* d_in, const int* in_sizes, int n_in,
                              void* d_out, int out_size) {
    const float* x    = (const float*)d_in[0];
    const float* xw   = (const float*)d_in[1];
    const float* emb  = (const float*)d_in[2];
    const float* wp   = (const float*)d_in[3];
    const float* wwin = (const float*)d_in[4];
    const float* bp   = (const float*)d_in[5];
    const float* T    = (const float*)d_in[6];
    const float* l1w  = (const float*)d_in[7];
    const float* l1b  = (const float*)d_in[8];
    const float* l2w  = (const float*)d_in[9];
    const float* l2b  = (const float*)d_in[10];
    float* out = (float*)d_out;

    cudaFuncSetAttribute(pexp_tc, cudaFuncAttributeMaxDynamicSharedMemorySize, PE_SMEM);
    cudaFuncSetAttribute(tc_gemm, cudaFuncAttributeMaxDynamicSharedMemorySize, SMEM_BYTES);

    prep_kernel<<<666, 256>>>(x, emb, wp, wwin);             // 0
    rowmax_tc<<<dim3(2, 40), 256>>>();                       // 1
    pexp_tc<<<dim3(2, 40), 256, PE_SMEM>>>();                // 2  (80 CTAs, one wave)
    tc_gemm<<<dim3(4, 32), 512, SMEM_BYTES>>>(0);            // 3  <- profiled slot
    tc_gemm<<<dim3(4, 32), 512, SMEM_BYTES>>>(1);            // 4
    pool_tc<<<dim3(28, 40), 256>>>();                        // 5
    xwagg_kernel<<<(Nn * Bb * 16 + 255) / 256, 256>>>(xw, T);// 6
    final_kernel<<<Nn, 128>>>(x, emb, bp, l1w, l1b, l2w, l2b, out); // 7
}